// round 2
// baseline (speedup 1.0000x reference)
#include <cuda_runtime.h>

#define BN 16
#define CN 1024
#define TN 16
#define PN 360          // H*W
#define KN 120
#define NCHUNK 64       // c-chunks for scores
#define CPC 16          // c per chunk
#define OUTROWS 482     // 1 + 120 + 1 + 360
#define TC 64           // transpose tile: c extent
#define TP 32           // transpose tile: p extent
#define NTHREADS 384

// scratch (no allocations allowed)
__device__ float g_partial[BN][NCHUNK][PN];
__device__ int   g_rank[BN][PN];

// ---------------------------------------------------------------------------
// Kernel A: two independent jobs fused into one grid.
//   blocks [0, 1024):          partial scores for frame 0
//   blocks [1024, 1024+3072):  frame-1 transpose  out[b,122+p,c] = x[b,c,1,p]
// ---------------------------------------------------------------------------
#define SCORE_BLOCKS (BN * NCHUNK)                       // 1024
#define T1_CT (CN / TC)                                  // 16 c-tiles
#define T1_PT ((PN + TP - 1) / TP)                       // 12 p-tiles
#define T1_BLOCKS (BN * T1_CT * T1_PT)                   // 3072

__global__ void __launch_bounds__(NTHREADS)
kernelA(const float* __restrict__ x, const float* __restrict__ cls,
        float* __restrict__ out) {
    __shared__ float tile[TC][TP + 1];
    const int bid = blockIdx.x;
    const int tid = threadIdx.x;
    const size_t cstride = (size_t)TN * PN;   // stride between c planes of x

    if (bid < SCORE_BLOCKS) {
        // ---- partial dot products, frame 0 ----
        int b = bid >> 6, chunk = bid & 63;
        int p = tid;
        if (p < PN) {
            const float* xb = x + ((size_t)b * CN + chunk * CPC) * cstride + p; // t=0
            const float* cb = cls + (size_t)b * TN * CN + chunk * CPC;          // cls[b,0,*]
            float a0 = 0.f, a1 = 0.f, a2 = 0.f, a3 = 0.f;
#pragma unroll
            for (int c = 0; c < CPC; c += 4) {
                a0 = fmaf(cb[c + 0], xb[(size_t)(c + 0) * cstride], a0);
                a1 = fmaf(cb[c + 1], xb[(size_t)(c + 1) * cstride], a1);
                a2 = fmaf(cb[c + 2], xb[(size_t)(c + 2) * cstride], a2);
                a3 = fmaf(cb[c + 3], xb[(size_t)(c + 3) * cstride], a3);
            }
            g_partial[b][chunk][p] = (a0 + a1) + (a2 + a3);
        }
    } else {
        // ---- frame-1 transpose: out[b, 122+p, c] = x[b, c, 1, p] ----
        int t = bid - SCORE_BLOCKS;
        int b  = t / (T1_CT * T1_PT);
        int r  = t % (T1_CT * T1_PT);
        int c0 = (r / T1_PT) * TC;
        int p0 = (r % T1_PT) * TP;

        // load: coalesced along p (TP consecutive floats per c row)
        for (int idx = tid; idx < TC * TP; idx += NTHREADS) {
            int cc = idx / TP, pp = idx % TP;
            int p = p0 + pp;
            tile[cc][pp] = (p < PN)
                ? x[((size_t)b * CN + c0 + cc) * cstride + (size_t)1 * PN + p]
                : 0.f;
        }
        __syncthreads();
        // store: coalesced along c (TC consecutive floats per out row)
        for (int idx = tid; idx < TP * TC; idx += NTHREADS) {
            int pp = idx / TC, cc = idx % TC;
            int p = p0 + pp;
            if (p < PN)
                out[((size_t)b * OUTROWS + 122 + p) * CN + c0 + cc] = tile[cc][pp];
        }
    }
}

// ---------------------------------------------------------------------------
// Kernel B: reduce partials -> score, exact stable descending rank (matches
// jax top_k tie-breaking: rank = #greater + #equal-with-smaller-index), and
// copy the two cls rows. Monotone transforms (/sqrt(c), softmax, /frame_max)
// cannot change this ordering.
// ---------------------------------------------------------------------------
__global__ void __launch_bounds__(NTHREADS)
rank_kernel(const float* __restrict__ cls, float* __restrict__ out) {
    int b = blockIdx.x;
    int p = threadIdx.x;
    __shared__ float s[PN];
    float v = 0.f;
    if (p < PN) {
#pragma unroll 8
        for (int k = 0; k < NCHUNK; ++k) v += g_partial[b][k][p];
        s[p] = v;
    }
    __syncthreads();
    if (p < PN) {
        int cnt = 0;
#pragma unroll 8
        for (int q = 0; q < PN; ++q) {
            float sq = s[q];
            cnt += (sq > v) || (sq == v && q < p);
        }
        g_rank[b][p] = cnt;
    }
    // out[b,0,:] = cls[b,0,:]; out[b,121,:] = cls[b,1,:]
    for (int c = threadIdx.x; c < CN; c += NTHREADS) {
        out[((size_t)b * OUTROWS + 0)   * CN + c] = cls[((size_t)b * TN + 0) * CN + c];
        out[((size_t)b * OUTROWS + 121) * CN + c] = cls[((size_t)b * TN + 1) * CN + c];
    }
}

// ---------------------------------------------------------------------------
// Kernel C: frame-0 scatter (reads are L2-resident after kernel A).
//   out[b, 1+rank[p], c] = x[b, c, 0, p]   for rank[p] < K
// ---------------------------------------------------------------------------
__global__ void __launch_bounds__(NTHREADS)
scatter0_kernel(const float* __restrict__ x, float* __restrict__ out) {
    __shared__ float tile[TC][TP + 1];
    __shared__ int   rk[TP];
    const int tid = threadIdx.x;
    int b  = blockIdx.x / (T1_CT * T1_PT);
    int r  = blockIdx.x % (T1_CT * T1_PT);
    int c0 = (r / T1_PT) * TC;
    int p0 = (r % T1_PT) * TP;
    const size_t cstride = (size_t)TN * PN;

    if (tid < TP) {
        int p = p0 + tid;
        rk[tid] = (p < PN) ? g_rank[b][p] : KN;
    }
    for (int idx = tid; idx < TC * TP; idx += NTHREADS) {
        int cc = idx / TP, pp = idx % TP;
        int p = p0 + pp;
        tile[cc][pp] = (p < PN)
            ? x[((size_t)b * CN + c0 + cc) * cstride + p]   // t = 0
            : 0.f;
    }
    __syncthreads();
    for (int idx = tid; idx < TP * TC; idx += NTHREADS) {
        int pp = idx / TC, cc = idx % TC;
        int rr = rk[pp];
        if (rr < KN)
            out[((size_t)b * OUTROWS + 1 + rr) * CN + c0 + cc] = tile[cc][pp];
    }
}

extern "C" void kernel_launch(void* const* d_in, const int* in_sizes, int n_in,
                              void* d_out, int out_size) {
    const float* x   = (const float*)d_in[0];   // [16,1024,16,12,30] f32
    const float* cls = (const float*)d_in[1];   // [16,16,1024] f32
    float* out = (float*)d_out;                 // [16,482,1024] f32

    kernelA<<<SCORE_BLOCKS + T1_BLOCKS, NTHREADS>>>(x, cls, out);
    rank_kernel<<<BN, NTHREADS>>>(cls, out);
    scatter0_kernel<<<T1_BLOCKS, NTHREADS>>>(x, out);
}

// round 3
// speedup vs baseline: 1.2513x; 1.2513x over previous
#include <cuda_runtime.h>

#define BN 16
#define CN 1024
#define TN 16
#define PN 360          // H*W
#define KN 120
#define NCHUNK 64       // c-chunks for scores
#define CPC 16          // c per chunk
#define OUTROWS 482     // 1 + 120 + 1 + 360
#define TC 64           // assemble tile: c extent
#define TP 32           // assemble tile: p extent

// scratch (no allocations allowed)
__device__ float g_partial[BN][NCHUNK][PN];
__device__ int   g_rank[BN][PN];

// ---------------------------------------------------------------------------
// K1: partial dot products, frame 0 only.
// s[b][p] = sum_c cls[b,0,c] * x[b,c,0,p]. 1024 blocks for occupancy,
// 16 fully-unrolled independent loads per thread for MLP.
// ---------------------------------------------------------------------------
__global__ void __launch_bounds__(384)
scores_kernel(const float* __restrict__ x, const float* __restrict__ cls) {
    int b = blockIdx.x >> 6, chunk = blockIdx.x & 63;
    int p = threadIdx.x;
    if (p >= PN) return;
    const size_t cstride = (size_t)TN * PN;
    const float* xb = x + ((size_t)b * CN + chunk * CPC) * cstride + p;  // t=0
    const float* cb = cls + (size_t)b * TN * CN + chunk * CPC;           // cls[b,0,*]

    float xv[CPC];
#pragma unroll
    for (int c = 0; c < CPC; ++c)           // 16 independent loads in flight
        xv[c] = xb[(size_t)c * cstride];
    float a0 = 0.f, a1 = 0.f, a2 = 0.f, a3 = 0.f;
#pragma unroll
    for (int c = 0; c < CPC; c += 4) {
        a0 = fmaf(cb[c + 0], xv[c + 0], a0);
        a1 = fmaf(cb[c + 1], xv[c + 1], a1);
        a2 = fmaf(cb[c + 2], xv[c + 2], a2);
        a3 = fmaf(cb[c + 3], xv[c + 3], a3);
    }
    g_partial[b][chunk][p] = (a0 + a1) + (a2 + a3);
}

// ---------------------------------------------------------------------------
// K2: reduce partials -> score, exact stable descending rank (matches jax
// top_k tie-breaking), copy the two cls rows. Monotone transforms
// (/sqrt(c), softmax, /frame_max) cannot change the ordering.
// ---------------------------------------------------------------------------
__global__ void __launch_bounds__(384)
rank_kernel(const float* __restrict__ cls, float* __restrict__ out) {
    int b = blockIdx.x;
    int p = threadIdx.x;
    __shared__ float s[PN];
    float v = 0.f;
    if (p < PN) {
#pragma unroll
        for (int k = 0; k < NCHUNK; ++k) v += g_partial[b][k][p];
        s[p] = v;
    }
    __syncthreads();
    if (p < PN) {
        int cnt = 0;
#pragma unroll 8
        for (int q = 0; q < PN; ++q) {
            float sq = s[q];
            cnt += (sq > v) || (sq == v && q < p);
        }
        g_rank[b][p] = cnt;
    }
    for (int c = threadIdx.x; c < CN; c += 384) {
        out[((size_t)b * OUTROWS + 0)   * CN + c] = cls[((size_t)b * TN + 0) * CN + c];
        out[((size_t)b * OUTROWS + 121) * CN + c] = cls[((size_t)b * TN + 1) * CN + c];
    }
}

// ---------------------------------------------------------------------------
// K3: transpose + scatter, both frames. 64c x 32p tile, 256 threads.
// Both gmem phases are constant-trip 8x unrolled (8 loads/stores in flight).
// smem tile[cc][pp] with stride 33: banks=(cc+pp)%32 -> conflict-free in
// both access patterns.
//   frame 0: out[b, 1+rank[p], c] = x[b,c,0,p]  (rank<K only; L2-resident read)
//   frame 1: out[b, 122+p,    c] = x[b,c,1,p]
// grid: x = 12 p-tiles, y = frame*16 + c-tile, z = b
// ---------------------------------------------------------------------------
__global__ void __launch_bounds__(256)
assemble_kernel(const float* __restrict__ x, float* __restrict__ out) {
    __shared__ float tile[TC][TP + 1];
    __shared__ int   rk[TP];
    const int tid   = threadIdx.x;
    const int p0    = blockIdx.x * TP;
    const int frame = blockIdx.y >> 4;
    const int c0    = (blockIdx.y & 15) * TC;
    const int b     = blockIdx.z;
    const size_t cstride = (size_t)TN * PN;
    const float* xbase = x + (size_t)b * CN * cstride + (size_t)frame * PN;

    if (tid < TP) {
        int p = p0 + tid;
        rk[tid] = (p < PN) ? g_rank[b][p] : KN;
    }

    // load: warp covers one cc row of 32 consecutive p (128B), 8 per thread
#pragma unroll
    for (int i = 0; i < (TC * TP) / 256; ++i) {
        int idx = tid + i * 256;
        int cc = idx >> 5, pp = idx & 31;
        int p = p0 + pp;
        float v = 0.f;
        if (p < PN) v = xbase[(size_t)(c0 + cc) * cstride + p];
        tile[cc][pp] = v;
    }
    __syncthreads();

    // store: warp covers 32 consecutive c of one out row (128B), 8 per thread
#pragma unroll
    for (int i = 0; i < (TP * TC) / 256; ++i) {
        int idx = tid + i * 256;
        int pp = idx >> 6, cc = idx & 63;
        int p = p0 + pp;
        if (p >= PN) continue;
        int row;
        if (frame == 0) {
            int r = rk[pp];
            if (r >= KN) continue;
            row = 1 + r;
        } else {
            row = 122 + p;
        }
        out[((size_t)b * OUTROWS + row) * CN + c0 + cc] = tile[cc][pp];
    }
}

extern "C" void kernel_launch(void* const* d_in, const int* in_sizes, int n_in,
                              void* d_out, int out_size) {
    const float* x   = (const float*)d_in[0];   // [16,1024,16,12,30] f32
    const float* cls = (const float*)d_in[1];   // [16,16,1024] f32
    float* out = (float*)d_out;                 // [16,482,1024] f32

    scores_kernel<<<BN * NCHUNK, 384>>>(x, cls);
    rank_kernel<<<BN, 384>>>(cls, out);
    assemble_kernel<<<dim3(12, 32, BN), 256>>>(x, out);
}

// round 4
// speedup vs baseline: 1.9200x; 1.5344x over previous
#include <cuda_runtime.h>

#define BN 16
#define CN 1024
#define TN 16
#define PN 360          // H*W
#define KN 120
#define NCHUNK 64       // c-chunks for scores (16 c each)
#define PARTS 256       // partial slots per b (= NCHUNK * 4 subgroups)
#define OUTROWS 482     // 1 + 120 + 1 + 360
#define TC 64           // assemble tile: c extent
#define TPP 64          // assemble tile: p extent

// scratch (no allocations allowed)
__device__ float g_partial[BN][PARTS][PN];
__device__ int   g_rank[BN][PN];

// ---------------------------------------------------------------------------
// K1: partial dot products, frame 0, all-vector loads.
// Block = (b, chunk of 16 c). Thread groups of 96 (cg = tid/96, i = tid%96,
// active i < 90): thread owns p-quad [4i, 4i+4) and c-range
// [chunk*16 + cg*4, +4). 4 independent LDG.128 per thread.
// ---------------------------------------------------------------------------
__global__ void __launch_bounds__(384)
scores_kernel(const float* __restrict__ x, const float* __restrict__ cls) {
    const int b = blockIdx.x >> 6, chunk = blockIdx.x & 63;
    const int cg = threadIdx.x / 96;          // 0..3
    const int i  = threadIdx.x % 96;          // p-quad index
    if (i >= 90) return;
    const int cbase = chunk * 16 + cg * 4;

    // x[b, cbase+c, t=0, p]: c-plane stride = TN*PN = 5760 floats = 1440 float4
    const float4* xb4 = (const float4*)(x + ((size_t)b * CN + cbase) * (TN * PN));
    const float*  cb  = cls + (size_t)b * TN * CN + cbase;   // cls[b,0,cbase..]

    float4 x0 = xb4[(size_t)0 * 1440 + i];
    float4 x1 = xb4[(size_t)1 * 1440 + i];
    float4 x2 = xb4[(size_t)2 * 1440 + i];
    float4 x3 = xb4[(size_t)3 * 1440 + i];
    float c0 = cb[0], c1 = cb[1], c2 = cb[2], c3 = cb[3];

    float4 acc;
    acc.x = fmaf(c0, x0.x, fmaf(c1, x1.x, fmaf(c2, x2.x, c3 * x3.x)));
    acc.y = fmaf(c0, x0.y, fmaf(c1, x1.y, fmaf(c2, x2.y, c3 * x3.y)));
    acc.z = fmaf(c0, x0.z, fmaf(c1, x1.z, fmaf(c2, x2.z, c3 * x3.z)));
    acc.w = fmaf(c0, x0.w, fmaf(c1, x1.w, fmaf(c2, x2.w, c3 * x3.w)));

    *(float4*)&g_partial[b][chunk * 4 + cg][4 * i] = acc;
}

// ---------------------------------------------------------------------------
// K2: reduce 256 partials -> score, exact stable descending rank (matches jax
// top_k tie-breaking: #greater + #equal-with-smaller-index), copy cls rows.
// Monotone transforms (/sqrt(c), softmax, /frame_max) cannot change ordering.
// ---------------------------------------------------------------------------
__global__ void __launch_bounds__(384)
rank_kernel(const float* __restrict__ cls, float* __restrict__ out) {
    const int b = blockIdx.x;
    const int p = threadIdx.x;
    __shared__ float s[PN];
    float v = 0.f;
    if (p < PN) {
#pragma unroll 16
        for (int k = 0; k < PARTS; ++k) v += g_partial[b][k][p];
        s[p] = v;
    }
    __syncthreads();
    if (p < PN) {
        int cnt = 0;
#pragma unroll 8
        for (int q = 0; q < PN; ++q) {
            float sq = s[q];
            cnt += (sq > v) || (sq == v && q < p);
        }
        g_rank[b][p] = cnt;
    }
    // out[b,0,:] = cls[b,0,:]; out[b,121,:] = cls[b,1,:]  (float4)
    if (threadIdx.x < 256) {
        const float4* c4 = (const float4*)(cls + (size_t)b * TN * CN);
        float4* o4 = (float4*)(out + (size_t)b * OUTROWS * CN);
        o4[threadIdx.x] = c4[threadIdx.x];                               // row 0
        o4[(size_t)121 * 256 + threadIdx.x] = c4[256 + threadIdx.x];     // row 121
    }
}

// ---------------------------------------------------------------------------
// K3: transpose + scatter, both frames, 64c x 64p tiles, 256 threads,
// all-vector gmem. smem tile[p][c] pad 65 (<=2-way conflicts, not binding).
//   frame 0: out[b, 1+rank[p], c] = x[b,c,0,p]  (rank<K; reads L2-resident)
//   frame 1: out[b, 122+p,    c] = x[b,c,1,p]
// grid: x = 6 p-tiles, y = frame*16 + c-tile, z = b
// ---------------------------------------------------------------------------
__global__ void __launch_bounds__(256)
assemble_kernel(const float* __restrict__ x, float* __restrict__ out) {
    __shared__ float tile[TPP][TC + 1];
    __shared__ int   rk[TPP];
    const int tid   = threadIdx.x;
    const int p0    = blockIdx.x * TPP;
    const int frame = blockIdx.y >> 4;
    const int c0    = (blockIdx.y & 15) * TC;
    const int b     = blockIdx.z;
    const float* xbase = x + ((size_t)b * CN) * (TN * PN) + (size_t)frame * PN;

    if (tid < TPP) {
        int p = p0 + tid;
        rk[tid] = (p < PN) ? g_rank[b][p] : KN;
    }

    // load: (64 c-rows) x (16 p-quads), LDG.128 along p, scalar STS
#pragma unroll
    for (int it = 0; it < (TC * (TPP / 4)) / 256; ++it) {   // 4 iters
        int idx = tid + it * 256;
        int cc = idx >> 4, pq = idx & 15;
        int p = p0 + 4 * pq;
        if (p < PN) {   // PN % 4 == 0 -> whole-quad validity
            float4 v = *(const float4*)(xbase + (size_t)(c0 + cc) * (TN * PN) + p);
            tile[4 * pq + 0][cc] = v.x;
            tile[4 * pq + 1][cc] = v.y;
            tile[4 * pq + 2][cc] = v.z;
            tile[4 * pq + 3][cc] = v.w;
        }
    }
    __syncthreads();

    // store: (64 p-rows) x (16 c-quads), scalar LDS, STG.128 along c
#pragma unroll
    for (int it = 0; it < (TPP * (TC / 4)) / 256; ++it) {   // 4 iters
        int idx = tid + it * 256;
        int pp = idx >> 4, cq = idx & 15;
        int p = p0 + pp;
        if (p >= PN) continue;
        int row;
        if (frame == 0) {
            int r = rk[pp];
            if (r >= KN) continue;
            row = 1 + r;
        } else {
            row = 122 + p;
        }
        float4 v;
        v.x = tile[pp][4 * cq + 0];
        v.y = tile[pp][4 * cq + 1];
        v.z = tile[pp][4 * cq + 2];
        v.w = tile[pp][4 * cq + 3];
        *(float4*)(out + ((size_t)b * OUTROWS + row) * CN + c0 + 4 * cq) = v;
    }
}

extern "C" void kernel_launch(void* const* d_in, const int* in_sizes, int n_in,
                              void* d_out, int out_size) {
    const float* x   = (const float*)d_in[0];   // [16,1024,16,12,30] f32
    const float* cls = (const float*)d_in[1];   // [16,16,1024] f32
    float* out = (float*)d_out;                 // [16,482,1024] f32

    scores_kernel<<<BN * NCHUNK, 384>>>(x, cls);
    rank_kernel<<<BN, 384>>>(cls, out);
    assemble_kernel<<<dim3(6, 32, BN), 256>>>(x, out);
}

// round 5
// speedup vs baseline: 2.0526x; 1.0691x over previous
#include <cuda_runtime.h>

#define BN 16
#define CN 1024
#define TN 16
#define PN 360          // H*W
#define KN 120
#define OUTROWS 482     // 1 + 120 + 1 + 360
#define CT 64           // tile: c extent
#define PT 64           // tile: p extent
#define NCT (CN / CT)   // 16 c-tiles
#define NPT 6           // ceil(PN / PT)
#define PLANE (TN * PN) // 5760 floats per (b,c) plane

// scratch (no allocations allowed)
__device__ float g_partial[BN][NCT][PN];
__device__ int   g_rank[BN][PN];

// ---------------------------------------------------------------------------
// K1 (fused single pass over x): block = (b, c-tile 64, p-tile 64).
// Loads frame-0 AND frame-1 p-spans of 64 c-planes (contiguous 2x256B per
// plane, frames 1440B apart -> same DRAM row) into smem, then:
//   - partial scores:  g_partial[b][ct][p] = sum_{c in tile} cls[b,0,c]*x0
//   - frame-1 output:  out[b, 122+p, c] = x1  (transposed, STG.128)
// ---------------------------------------------------------------------------
__global__ void __launch_bounds__(256)
fused_kernel(const float* __restrict__ x, const float* __restrict__ cls,
             float* __restrict__ out) {
    __shared__ float tile[2 * PT][CT + 1];   // [f*64 + p_local][cc]
    __shared__ float scls[CT];
    __shared__ float sacc[4][PT];
    const int tid = threadIdx.x;
    const int b  = blockIdx.z;
    const int c0 = blockIdx.y * CT;
    const int p0 = blockIdx.x * PT;
    const float* xplane = x + ((size_t)b * CN + c0) * PLANE;

    if (tid < CT) scls[tid] = cls[(size_t)b * TN * CN + c0 + tid];

    // load: 64 c-rows x 32 quads (2 frames x 16 p-quads), LDG.128
#pragma unroll
    for (int it = 0; it < (CT * 32) / 256; ++it) {      // 8 iters
        int idx = tid + it * 256;
        int cc = idx >> 5, q = idx & 31;
        int f = q >> 4, pq = q & 15;
        int p = p0 + 4 * pq;
        float4 v = make_float4(0.f, 0.f, 0.f, 0.f);
        if (p < PN)
            v = *(const float4*)(xplane + (size_t)cc * PLANE + f * PN + p);
        int r = f * PT + 4 * pq;
        tile[r + 0][cc] = v.x;
        tile[r + 1][cc] = v.y;
        tile[r + 2][cc] = v.z;
        tile[r + 3][cc] = v.w;
    }
    __syncthreads();

    // partial scores from frame-0 half (conflict-free: bank=(pl+c)%32)
    {
        int pl = tid & 63, csub = tid >> 6;
        float a = 0.f;
#pragma unroll
        for (int j = 0; j < 16; ++j) {
            int c = csub * 16 + j;
            a = fmaf(scls[c], tile[pl][c], a);
        }
        sacc[csub][pl] = a;
    }

    // frame-1 transposed store: 64 p-rows x 16 c-quads, STG.128
#pragma unroll
    for (int it = 0; it < (PT * (CT / 4)) / 256; ++it) {   // 4 iters
        int idx = tid + it * 256;
        int pl = idx >> 4, cq = idx & 15;
        int p = p0 + pl;
        if (p < PN) {
            float4 v;
            v.x = tile[PT + pl][4 * cq + 0];
            v.y = tile[PT + pl][4 * cq + 1];
            v.z = tile[PT + pl][4 * cq + 2];
            v.w = tile[PT + pl][4 * cq + 3];
            *(float4*)(out + ((size_t)b * OUTROWS + 122 + p) * CN + c0 + 4 * cq) = v;
        }
    }
    __syncthreads();

    if (tid < PT) {
        int p = p0 + tid;
        if (p < PN)
            g_partial[b][blockIdx.y][p] =
                (sacc[0][tid] + sacc[1][tid]) + (sacc[2][tid] + sacc[3][tid]);
    }
}

// ---------------------------------------------------------------------------
// K2: reduce 16 partials -> score, exact stable descending rank (matches jax
// top_k tie-breaking: #greater + #equal-with-smaller-index), copy cls rows.
// Monotone transforms (/sqrt(c), softmax, /frame_max) cannot change ordering.
// ---------------------------------------------------------------------------
__global__ void __launch_bounds__(384)
rank_kernel(const float* __restrict__ cls, float* __restrict__ out) {
    const int b = blockIdx.x;
    const int p = threadIdx.x;
    __shared__ float s[PN];
    float v = 0.f;
    if (p < PN) {
#pragma unroll
        for (int k = 0; k < NCT; ++k) v += g_partial[b][k][p];
        s[p] = v;
    }
    __syncthreads();
    if (p < PN) {
        int cnt = 0;
#pragma unroll 8
        for (int q = 0; q < PN; ++q) {
            float sq = s[q];
            cnt += (sq > v) || (sq == v && q < p);
        }
        g_rank[b][p] = cnt;
    }
    // out[b,0,:] = cls[b,0,:]; out[b,121,:] = cls[b,1,:]  (float4)
    if (threadIdx.x < 256) {
        const float4* c4 = (const float4*)(cls + (size_t)b * TN * CN);
        float4* o4 = (float4*)(out + (size_t)b * OUTROWS * CN);
        o4[threadIdx.x] = c4[threadIdx.x];                            // row 0
        o4[(size_t)121 * 256 + threadIdx.x] = c4[256 + threadIdx.x];  // row 121
    }
}

// ---------------------------------------------------------------------------
// K3: frame-0 scatter (reads L2-resident after K1).
//   out[b, 1+rank[p], c] = x[b,c,0,p]   for rank[p] < K
// ---------------------------------------------------------------------------
__global__ void __launch_bounds__(256)
scatter0_kernel(const float* __restrict__ x, float* __restrict__ out) {
    __shared__ float tile[PT][CT + 1];
    __shared__ int   rk[PT];
    const int tid = threadIdx.x;
    const int b  = blockIdx.z;
    const int c0 = blockIdx.y * CT;
    const int p0 = blockIdx.x * PT;
    const float* xplane = x + ((size_t)b * CN + c0) * PLANE;   // t = 0

    if (tid < PT) {
        int p = p0 + tid;
        rk[tid] = (p < PN) ? g_rank[b][p] : KN;
    }

#pragma unroll
    for (int it = 0; it < (CT * (PT / 4)) / 256; ++it) {   // 4 iters
        int idx = tid + it * 256;
        int cc = idx >> 4, pq = idx & 15;
        int p = p0 + 4 * pq;
        if (p < PN) {
            float4 v = *(const float4*)(xplane + (size_t)cc * PLANE + p);
            tile[4 * pq + 0][cc] = v.x;
            tile[4 * pq + 1][cc] = v.y;
            tile[4 * pq + 2][cc] = v.z;
            tile[4 * pq + 3][cc] = v.w;
        }
    }
    __syncthreads();

#pragma unroll
    for (int it = 0; it < (PT * (CT / 4)) / 256; ++it) {   // 4 iters
        int idx = tid + it * 256;
        int pl = idx >> 4, cq = idx & 15;
        int r = rk[pl];
        if (r >= KN) continue;
        float4 v;
        v.x = tile[pl][4 * cq + 0];
        v.y = tile[pl][4 * cq + 1];
        v.z = tile[pl][4 * cq + 2];
        v.w = tile[pl][4 * cq + 3];
        *(float4*)(out + ((size_t)b * OUTROWS + 1 + r) * CN + c0 + 4 * cq) = v;
    }
}

extern "C" void kernel_launch(void* const* d_in, const int* in_sizes, int n_in,
                              void* d_out, int out_size) {
    const float* x   = (const float*)d_in[0];   // [16,1024,16,12,30] f32
    const float* cls = (const float*)d_in[1];   // [16,16,1024] f32
    float* out = (float*)d_out;                 // [16,482,1024] f32

    fused_kernel<<<dim3(NPT, NCT, BN), 256>>>(x, cls, out);
    rank_kernel<<<BN, 384>>>(cls, out);
    scatter0_kernel<<<dim3(NPT, NCT, BN), 256>>>(x, out);
}